// round 8
// baseline (speedup 1.0000x reference)
#include <cuda_runtime.h>
#include <cuda_fp16.h>
#include <cstdint>

// ============================================================================
// Problem constants
// ============================================================================
#define EDIM 256      // E
#define HIDN 512      // 2E
#define KIN  768      // 3E
#define BTOT 131072

// ============================================================================
// Device scratch (allocation-free rule: __device__ globals)
// ============================================================================
__device__ float  g_M[6 * EDIM * EDIM];                  // M_i = Wo_i @ Wv_i
__device__ float  g_cvec[6 * EDIM];                      // c_i = Wo_i @ bv_i + bo_i
__device__ float  g_b1eff[HIDN];                         // b1 + Kvec @ W1^T
__device__ __align__(16) __half g_B1h[HIDN * KIN];       // folded W1, fp16 [N=512][K=768]
__device__ __align__(16) __half g_W2h[EDIM * HIDN];      // W2 fp16 [N=256][K=512]
__device__ __align__(16) __half g_H[(size_t)BTOT * HIDN];// hidden fp16 [131072][512]
__device__ __align__(16) __half g_Xh[(size_t)BTOT * KIN];// X fp16 [131072][768] (g|d|c)

// idx(r,q): module index whose kv-input is block r and query/output is block q
__constant__ int c_IDX[3][3] = {{-1, 2, 4}, {0, -1, 5}, {1, 3, -1}};

// ============================================================================
// PTX helpers (baseline sm_80+ features only: mma.sync / ldmatrix / cp.async)
// ============================================================================
__device__ __forceinline__ uint32_t smem_u32(const void* p) {
    uint32_t a;
    asm("{ .reg .u64 t; cvta.to.shared.u64 t, %1; cvt.u32.u64 %0, t; }" : "=r"(a) : "l"(p));
    return a;
}

__device__ __forceinline__ void cp_async16(uint32_t saddr, const void* gaddr) {
    asm volatile("cp.async.cg.shared.global [%0], [%1], 16;" :: "r"(saddr), "l"(gaddr));
}
__device__ __forceinline__ void cp_commit() { asm volatile("cp.async.commit_group;" ::: "memory"); }
__device__ __forceinline__ void cp_wait0()  { asm volatile("cp.async.wait_group 0;" ::: "memory"); }

__device__ __forceinline__ void ldm_x4(uint32_t& r0, uint32_t& r1, uint32_t& r2, uint32_t& r3,
                                       uint32_t addr) {
    asm volatile("ldmatrix.sync.aligned.m8n8.x4.shared.b16 {%0,%1,%2,%3}, [%4];"
                 : "=r"(r0), "=r"(r1), "=r"(r2), "=r"(r3) : "r"(addr));
}

// fp16-accumulate MMA: D(f16x2 pair) = A*B + C ; C/D in 2 b32 regs
__device__ __forceinline__ void mma16816h(uint32_t* c, uint32_t a0, uint32_t a1, uint32_t a2,
                                          uint32_t a3, uint32_t b0, uint32_t b1) {
    asm volatile(
        "mma.sync.aligned.m16n8k16.row.col.f16.f16.f16.f16 "
        "{%0,%1}, {%2,%3,%4,%5}, {%6,%7}, {%0,%1};"
        : "+r"(c[0]), "+r"(c[1])
        : "r"(a0), "r"(a1), "r"(a2), "r"(a3), "r"(b0), "r"(b1));
}

// XOR swizzle for a [128 rows][64 halves] tile (128B rows, 16B units, 8-way)
__device__ __forceinline__ uint32_t swz(uint32_t row, uint32_t k) {
    return row * 128u + ((((k >> 3) ^ (row & 7)) << 4) | ((k & 7) * 2u));
}

// ============================================================================
// Precompute kernels (validated fast in R4; unchanged)
// ============================================================================

__global__ void __launch_bounds__(256) k_M(const float* __restrict__ Wo,
                                           const float* __restrict__ Wv) {
    const int i  = blockIdx.z;
    const int k0 = blockIdx.x * 64, e0 = blockIdx.y * 64;
    const int tid = threadIdx.x;
    __shared__ float sA[64][17];
    __shared__ float sB[16][65];
    const float* A  = Wo + i * 65536;
    const float* Bm = Wv + i * 65536;
    float acc[4][4] = {};
    const int ty = tid >> 4, tx = tid & 15;
    for (int m0 = 0; m0 < 256; m0 += 16) {
        {
            int e = tid >> 4, mm = tid & 15;
#pragma unroll
            for (int r = 0; r < 4; r++)
                sA[r * 16 + e][mm] = A[(e0 + r * 16 + e) * 256 + m0 + mm];
        }
        {
            int mm = tid >> 6, kk = tid & 63;
#pragma unroll
            for (int r = 0; r < 4; r++)
                sB[r * 4 + mm][kk] = Bm[(m0 + r * 4 + mm) * 256 + k0 + kk];
        }
        __syncthreads();
#pragma unroll
        for (int kk = 0; kk < 16; kk++) {
            float a[4], b[4];
#pragma unroll
            for (int x = 0; x < 4; x++) a[x] = sA[ty * 4 + x][kk];
#pragma unroll
            for (int x = 0; x < 4; x++) b[x] = sB[kk][tx * 4 + x];
#pragma unroll
            for (int x = 0; x < 4; x++)
#pragma unroll
                for (int y = 0; y < 4; y++) acc[x][y] += a[x] * b[y];
        }
        __syncthreads();
    }
#pragma unroll
    for (int x = 0; x < 4; x++)
#pragma unroll
        for (int y = 0; y < 4; y++)
            g_M[i * 65536 + (e0 + ty * 4 + x) * 256 + k0 + tx * 4 + y] = acc[x][y];
}

__global__ void k_cvec(const float* __restrict__ Wo, const float* __restrict__ bv,
                       const float* __restrict__ bo) {
    int i = blockIdx.x, e = threadIdx.x;
    const float* w = Wo + i * 65536 + e * 256;
    const float* b = bv + i * 256;
    float a0 = 0.f, a1 = 0.f, a2 = 0.f, a3 = 0.f;
#pragma unroll 4
    for (int m = 0; m < 256; m += 4) {
        a0 += w[m + 0] * b[m + 0];
        a1 += w[m + 1] * b[m + 1];
        a2 += w[m + 2] * b[m + 2];
        a3 += w[m + 3] * b[m + 3];
    }
    g_cvec[i * 256 + e] = bo[i * 256 + e] + (a0 + a1) + (a2 + a3);
}

__global__ void __launch_bounds__(256) k_B1(const float* __restrict__ W1) {
    const int k0 = blockIdx.x * 64, n0 = blockIdx.y * 64;
    const int r = k0 >> 8;
    const int kp0 = k0 & 255;
    const int tid = threadIdx.x;
    __shared__ float sA[64][17];
    __shared__ float sB[16][65];
    float acc[4][4] = {};
    const int ty = tid >> 4, tx = tid & 15;
    for (int q = 0; q < 3; q++) {
        if (q == r) continue;
        const float* Mb = g_M + c_IDX[r][q] * 65536;
        for (int e0 = 0; e0 < 256; e0 += 16) {
            {
                int n = tid >> 4, ee = tid & 15;
#pragma unroll
                for (int rr = 0; rr < 4; rr++)
                    sA[rr * 16 + n][ee] = W1[(n0 + rr * 16 + n) * KIN + q * 256 + e0 + ee];
            }
            {
                int ee = tid >> 6, kk = tid & 63;
#pragma unroll
                for (int rr = 0; rr < 4; rr++)
                    sB[rr * 4 + ee][kk] = Mb[(e0 + rr * 4 + ee) * 256 + kp0 + kk];
            }
            __syncthreads();
#pragma unroll
            for (int kk = 0; kk < 16; kk++) {
                float a[4], b[4];
#pragma unroll
                for (int x = 0; x < 4; x++) a[x] = sA[ty * 4 + x][kk];
#pragma unroll
                for (int x = 0; x < 4; x++) b[x] = sB[kk][tx * 4 + x];
#pragma unroll
                for (int x = 0; x < 4; x++)
#pragma unroll
                    for (int y = 0; y < 4; y++) acc[x][y] += a[x] * b[y];
            }
            __syncthreads();
        }
    }
#pragma unroll
    for (int x = 0; x < 4; x++)
#pragma unroll
        for (int y = 0; y < 4; y++) {
            int n = n0 + ty * 4 + x, k = k0 + tx * 4 + y;
            g_B1h[n * KIN + k] = __float2half_rn(W1[n * KIN + k] + acc[x][y]);
        }
}

__global__ void __launch_bounds__(256) k_b1eff(const float* __restrict__ W1,
                                               const float* __restrict__ b1) {
    const int n = blockIdx.x;
    const int tid = threadIdx.x;
    float p = 0.f;
#pragma unroll
    for (int jj = 0; jj < 3; jj++) {
        int j = jj * 256 + tid;
        int q = j >> 8, e = j & 255;
        float cs = g_cvec[(2 * q) * 256 + e] + g_cvec[(2 * q + 1) * 256 + e];
        p += cs * W1[n * KIN + j];
    }
    __shared__ float red[256];
    red[tid] = p;
    __syncthreads();
#pragma unroll
    for (int s = 128; s > 0; s >>= 1) {
        if (tid < s) red[tid] += red[tid + s];
        __syncthreads();
    }
    if (tid == 0) g_b1eff[n] = b1[n] + red[0];
}

__global__ void k_W2h(const float* __restrict__ W2) {
    int idx = blockIdx.x * 256 + threadIdx.x;
    if (idx < EDIM * HIDN) g_W2h[idx] = __float2half_rn(W2[idx]);
}

// X (g|d|c fp32) -> g_Xh fp16, [B][768] row-major. One float4 per thread-iter.
__global__ void __launch_bounds__(1024) k_Xh(const float* __restrict__ gE,
                                             const float* __restrict__ dE,
                                             const float* __restrict__ cE) {
    const float* srcs[3] = {gE, dE, cE};
    const int s = blockIdx.y;
    const float* src = srcs[s];
    size_t j = (size_t)blockIdx.x * 1024 + threadIdx.x;  // over B*64 float4s
    size_t row = j >> 6;
    int c4 = (int)(j & 63);
    float4 f = *(const float4*)(src + row * 256 + c4 * 4);
    __half2 h0 = __floats2half2_rn(f.x, f.y);
    __half2 h1 = __floats2half2_rn(f.z, f.w);
    uint2 u = { *(uint32_t*)&h0, *(uint32_t*)&h1 };
    *(uint2*)(g_Xh + row * KIN + s * 256 + c4 * 4) = u;
}

// ============================================================================
// GEMM1: hidden[B,512] = relu(Xh[B,768] @ B1h^T + b1eff)
// 128 thr / 4 warps (2x2), CTA tile 128x128, warp tile 64x64, K-chunk 64.
// fp16-accumulate MMA, promoted to fp32 masters every 64-K chunk.
// ============================================================================
#define SM_A0 0
#define SM_A1 16384
#define SM_B0 32768
#define SM_B1 49152
#define SMEM_G 65536

__global__ void __launch_bounds__(128, 2)
gemm1(const float* __restrict__ unused0) {
    extern __shared__ char smem[];
    const uint32_t sb = smem_u32(smem);
    const int tid = threadIdx.x;
    const int wid = tid >> 5, lane = tid & 31;
    const int m0 = blockIdx.y * 128;
    const int n0 = blockIdx.x * 128;
    const int wm = (wid >> 1) * 64;
    const int wn = (wid & 1) * 64;

    float acc[4][8][4];
#pragma unroll
    for (int i = 0; i < 4; i++)
#pragma unroll
        for (int j = 0; j < 8; j++)
#pragma unroll
            for (int v = 0; v < 4; v++) acc[i][j][v] = 0.f;

    // prologue: buffer 0 — A from g_Xh, B from g_B1h, both cp.async (8x16B each)
    {
#pragma unroll
        for (int i = 0; i < 8; i++) {
            int idx = i * 128 + tid;
            int row = idx >> 3, c = idx & 7;
            cp_async16(sb + SM_A0 + swz(row, c * 8), g_Xh + (size_t)(m0 + row) * KIN + c * 8);
            cp_async16(sb + SM_B0 + swz(row, c * 8), g_B1h + (size_t)(n0 + row) * KIN + c * 8);
        }
        cp_commit();
        cp_wait0();
        __syncthreads();
    }

    const int NITER = 12;
    for (int kc = 0; kc < NITER; kc++) {
        const uint32_t Abase = sb + (kc & 1 ? SM_A1 : SM_A0);
        const uint32_t Bbase = sb + (kc & 1 ? SM_B1 : SM_B0);
        const int nxt = kc + 1;

        if (nxt < NITER) {
            uint32_t AbaseN = sb + (nxt & 1 ? SM_A1 : SM_A0);
            uint32_t BbaseN = sb + (nxt & 1 ? SM_B1 : SM_B0);
#pragma unroll
            for (int i = 0; i < 8; i++) {
                int idx = i * 128 + tid;
                int row = idx >> 3, c = idx & 7;
                cp_async16(AbaseN + swz(row, c * 8),
                           g_Xh + (size_t)(m0 + row) * KIN + nxt * 64 + c * 8);
                cp_async16(BbaseN + swz(row, c * 8),
                           g_B1h + (size_t)(n0 + row) * KIN + nxt * 64 + c * 8);
            }
            cp_commit();
        }

        // fp16 chunk accumulators (zeroed per kc)
        uint32_t acch[4][8][2];
#pragma unroll
        for (int i = 0; i < 4; i++)
#pragma unroll
            for (int j = 0; j < 8; j++) { acch[i][j][0] = 0u; acch[i][j][1] = 0u; }

#pragma unroll
        for (int ks = 0; ks < 64; ks += 16) {
            uint32_t a[4][4], b[16];
#pragma unroll
            for (int t = 0; t < 4; t++) {
                uint32_t row = wm + t * 16 + (lane & 15);
                uint32_t kk  = ks + (lane >> 4) * 8;
                ldm_x4(a[t][0], a[t][1], a[t][2], a[t][3], Abase + swz(row, kk));
            }
#pragma unroll
            for (int h = 0; h < 4; h++) {
                int g = lane >> 3, ri = lane & 7;
                uint32_t nrow = wn + h * 16 + (g >> 1) * 8 + ri;
                uint32_t kk   = ks + (g & 1) * 8;
                ldm_x4(b[h * 4 + 0], b[h * 4 + 1], b[h * 4 + 2], b[h * 4 + 3],
                       Bbase + swz(nrow, kk));
            }
#pragma unroll
            for (int mt = 0; mt < 4; mt++)
#pragma unroll
                for (int nt = 0; nt < 8; nt++)
                    mma16816h(acch[mt][nt], a[mt][0], a[mt][1], a[mt][2], a[mt][3],
                              b[nt * 2], b[nt * 2 + 1]);
        }

        // promote chunk to fp32 masters
#pragma unroll
        for (int mt = 0; mt < 4; mt++)
#pragma unroll
            for (int nt = 0; nt < 8; nt++) {
                float2 f01 = __half22float2(*(__half2*)&acch[mt][nt][0]);
                float2 f23 = __half22float2(*(__half2*)&acch[mt][nt][1]);
                acc[mt][nt][0] += f01.x;
                acc[mt][nt][1] += f01.y;
                acc[mt][nt][2] += f23.x;
                acc[mt][nt][3] += f23.y;
            }

        if (nxt < NITER) cp_wait0();
        __syncthreads();
    }

    // epilogue: relu(acc + b1eff) -> fp16 g_H
#pragma unroll
    for (int mt = 0; mt < 4; mt++) {
#pragma unroll
        for (int nt = 0; nt < 8; nt++) {
            int n = n0 + wn + nt * 8 + (lane & 3) * 2;
            float bia0 = g_b1eff[n], bia1 = g_b1eff[n + 1];
            int r0 = m0 + wm + mt * 16 + (lane >> 2);
            float v0 = fmaxf(acc[mt][nt][0] + bia0, 0.f);
            float v1 = fmaxf(acc[mt][nt][1] + bia1, 0.f);
            float v2 = fmaxf(acc[mt][nt][2] + bia0, 0.f);
            float v3 = fmaxf(acc[mt][nt][3] + bia1, 0.f);
            __half2 h01 = __floats2half2_rn(v0, v1);
            __half2 h23 = __floats2half2_rn(v2, v3);
            *(__half2*)(g_H + (size_t)r0 * HIDN + n)       = h01;
            *(__half2*)(g_H + (size_t)(r0 + 8) * HIDN + n) = h23;
        }
    }
}

// ============================================================================
// GEMM2: out[B,256] = g_H[B,512] @ W2h^T + b2 (fp16-accum + promotion)
// ============================================================================
__global__ void __launch_bounds__(128, 2)
gemm2(const float* __restrict__ b2, float* __restrict__ out) {
    extern __shared__ char smem[];
    const uint32_t sb = smem_u32(smem);
    const int tid = threadIdx.x;
    const int wid = tid >> 5, lane = tid & 31;
    const int m0 = blockIdx.y * 128;
    const int n0 = blockIdx.x * 128;
    const int wm = (wid >> 1) * 64;
    const int wn = (wid & 1) * 64;

    float acc[4][8][4];
#pragma unroll
    for (int i = 0; i < 4; i++)
#pragma unroll
        for (int j = 0; j < 8; j++)
#pragma unroll
            for (int v = 0; v < 4; v++) acc[i][j][v] = 0.f;

    // prologue buffer 0
    {
#pragma unroll
        for (int i = 0; i < 8; i++) {
            int idx = i * 128 + tid;
            int row = idx >> 3, c = idx & 7;
            cp_async16(sb + SM_A0 + swz(row, c * 8), g_H + (size_t)(m0 + row) * HIDN + c * 8);
            cp_async16(sb + SM_B0 + swz(row, c * 8), g_W2h + (size_t)(n0 + row) * HIDN + c * 8);
        }
        cp_commit();
        cp_wait0();
        __syncthreads();
    }

    const int NITER = 8;
    for (int kc = 0; kc < NITER; kc++) {
        const uint32_t Abase = sb + (kc & 1 ? SM_A1 : SM_A0);
        const uint32_t Bbase = sb + (kc & 1 ? SM_B1 : SM_B0);
        const int nxt = kc + 1;

        if (nxt < NITER) {
            uint32_t AbaseN = sb + (nxt & 1 ? SM_A1 : SM_A0);
            uint32_t BbaseN = sb + (nxt & 1 ? SM_B1 : SM_B0);
#pragma unroll
            for (int i = 0; i < 8; i++) {
                int idx = i * 128 + tid;
                int row = idx >> 3, c = idx & 7;
                cp_async16(AbaseN + swz(row, c * 8),
                           g_H + (size_t)(m0 + row) * HIDN + nxt * 64 + c * 8);
                cp_async16(BbaseN + swz(row, c * 8),
                           g_W2h + (size_t)(n0 + row) * HIDN + nxt * 64 + c * 8);
            }
            cp_commit();
        }

        uint32_t acch[4][8][2];
#pragma unroll
        for (int i = 0; i < 4; i++)
#pragma unroll
            for (int j = 0; j < 8; j++) { acch[i][j][0] = 0u; acch[i][j][1] = 0u; }

#pragma unroll
        for (int ks = 0; ks < 64; ks += 16) {
            uint32_t a[4][4], b[16];
#pragma unroll
            for (int t = 0; t < 4; t++) {
                uint32_t row = wm + t * 16 + (lane & 15);
                uint32_t kk  = ks + (lane >> 4) * 8;
                ldm_x4(a[t][0], a[t][1], a[t][2], a[t][3], Abase + swz(row, kk));
            }
#pragma unroll
            for (int h = 0; h < 4; h++) {
                int g = lane >> 3, ri = lane & 7;
                uint32_t nrow = wn + h * 16 + (g >> 1) * 8 + ri;
                uint32_t kk   = ks + (g & 1) * 8;
                ldm_x4(b[h * 4 + 0], b[h * 4 + 1], b[h * 4 + 2], b[h * 4 + 3],
                       Bbase + swz(nrow, kk));
            }
#pragma unroll
            for (int mt = 0; mt < 4; mt++)
#pragma unroll
                for (int nt = 0; nt < 8; nt++)
                    mma16816h(acch[mt][nt], a[mt][0], a[mt][1], a[mt][2], a[mt][3],
                              b[nt * 2], b[nt * 2 + 1]);
        }

#pragma unroll
        for (int mt = 0; mt < 4; mt++)
#pragma unroll
            for (int nt = 0; nt < 8; nt++) {
                float2 f01 = __half22float2(*(__half2*)&acch[mt][nt][0]);
                float2 f23 = __half22float2(*(__half2*)&acch[mt][nt][1]);
                acc[mt][nt][0] += f01.x;
                acc[mt][nt][1] += f01.y;
                acc[mt][nt][2] += f23.x;
                acc[mt][nt][3] += f23.y;
            }

        if (nxt < NITER) cp_wait0();
        __syncthreads();
    }

    // epilogue: acc + b2 -> fp32 out
#pragma unroll
    for (int mt = 0; mt < 4; mt++) {
#pragma unroll
        for (int nt = 0; nt < 8; nt++) {
            int n = n0 + wn + nt * 8 + (lane & 3) * 2;
            float bia0 = b2[n], bia1 = b2[n + 1];
            int r0 = m0 + wm + mt * 16 + (lane >> 2);
            float2 o01 = { acc[mt][nt][0] + bia0, acc[mt][nt][1] + bia1 };
            float2 o23 = { acc[mt][nt][2] + bia0, acc[mt][nt][3] + bia1 };
            *(float2*)(out + (size_t)r0 * EDIM + n)       = o01;
            *(float2*)(out + (size_t)(r0 + 8) * EDIM + n) = o23;
        }
    }
}

// ============================================================================
// kernel_launch
// Input order: g, d, c, Wq, Wk, Wv, bq, bk, bv, Wo, bo, W1, b1, W2, b2
// ============================================================================
extern "C" void kernel_launch(void* const* d_in, const int* in_sizes, int n_in,
                              void* d_out, int out_size) {
    const float* g  = (const float*)d_in[0];
    const float* dd = (const float*)d_in[1];
    const float* cc = (const float*)d_in[2];
    const float* Wv = (const float*)d_in[5];
    const float* bv = (const float*)d_in[8];
    const float* Wo = (const float*)d_in[9];
    const float* bo = (const float*)d_in[10];
    const float* W1 = (const float*)d_in[11];
    const float* b1 = (const float*)d_in[12];
    const float* W2 = (const float*)d_in[13];
    const float* b2 = (const float*)d_in[14];
    const int B = in_sizes[0] / EDIM;

    // Weight precompute + X fp16 conversion
    k_Xh   <<<dim3((B * 64) / 1024, 3), 1024>>>(g, dd, cc);
    k_M    <<<dim3(4, 4, 6), 256>>>(Wo, Wv);
    k_cvec <<<6, 256>>>(Wo, bv, bo);
    k_B1   <<<dim3(12, 8), 256>>>(W1);
    k_b1eff<<<HIDN, 256>>>(W1, b1);
    k_W2h  <<<512, 256>>>(W2);

    cudaFuncSetAttribute(gemm1, cudaFuncAttributeMaxDynamicSharedMemorySize, SMEM_G);
    cudaFuncSetAttribute(gemm2, cudaFuncAttributeMaxDynamicSharedMemorySize, SMEM_G);

    gemm1<<<dim3(4, B / 128), 128, SMEM_G>>>(g);
    gemm2<<<dim3(2, B / 128), 128, SMEM_G>>>(b2, (float*)d_out);
}

// round 9
// speedup vs baseline: 1.2630x; 1.2630x over previous
#include <cuda_runtime.h>
#include <cuda_fp16.h>
#include <cstdint>

// ============================================================================
// Problem constants
// ============================================================================
#define EDIM 256      // E
#define HIDN 512      // 2E
#define KIN  768      // 3E
#define BTOT 131072

// ============================================================================
// Device scratch (allocation-free rule: __device__ globals)
// ============================================================================
__device__ float  g_M[6 * EDIM * EDIM];                  // M_i = Wo_i @ Wv_i (atomic-accum)
__device__ float  g_B1f[HIDN * KIN];                     // fold term, fp32 (atomic-accum)
__device__ float  g_cvec[6 * EDIM];                      // c_i = Wo_i @ bv_i + bo_i
__device__ float  g_b1eff[HIDN];                         // b1 + Kvec @ W1^T
__device__ __align__(16) __half g_B1h[HIDN * KIN];       // folded W1, fp16 [N=512][K=768]
__device__ __align__(16) __half g_W2h[EDIM * HIDN];      // W2 fp16 [N=256][K=512]
__device__ __align__(16) __half g_H[(size_t)BTOT * HIDN];// hidden fp16 [131072][512]

// ============================================================================
// PTX helpers (baseline sm_80+ features only: mma.sync / ldmatrix / cp.async)
// ============================================================================
__device__ __forceinline__ uint32_t smem_u32(const void* p) {
    uint32_t a;
    asm("{ .reg .u64 t; cvta.to.shared.u64 t, %1; cvt.u32.u64 %0, t; }" : "=r"(a) : "l"(p));
    return a;
}

__device__ __forceinline__ void cp_async16(uint32_t saddr, const void* gaddr) {
    asm volatile("cp.async.cg.shared.global [%0], [%1], 16;" :: "r"(saddr), "l"(gaddr));
}
__device__ __forceinline__ void cp_commit() { asm volatile("cp.async.commit_group;" ::: "memory"); }
__device__ __forceinline__ void cp_wait0()  { asm volatile("cp.async.wait_group 0;" ::: "memory"); }

__device__ __forceinline__ void ldm_x4(uint32_t& r0, uint32_t& r1, uint32_t& r2, uint32_t& r3,
                                       uint32_t addr) {
    asm volatile("ldmatrix.sync.aligned.m8n8.x4.shared.b16 {%0,%1,%2,%3}, [%4];"
                 : "=r"(r0), "=r"(r1), "=r"(r2), "=r"(r3) : "r"(addr));
}

__device__ __forceinline__ void mma16816(float* c, uint32_t a0, uint32_t a1, uint32_t a2,
                                         uint32_t a3, uint32_t b0, uint32_t b1) {
    asm volatile(
        "mma.sync.aligned.m16n8k16.row.col.f32.f16.f16.f32 "
        "{%0,%1,%2,%3}, {%4,%5,%6,%7}, {%8,%9}, {%0,%1,%2,%3};"
        : "+f"(c[0]), "+f"(c[1]), "+f"(c[2]), "+f"(c[3])
        : "r"(a0), "r"(a1), "r"(a2), "r"(a3), "r"(b0), "r"(b1));
}

// XOR swizzle for a [128 rows][64 halves] tile (128B rows, 16B units, 8-way)
__device__ __forceinline__ uint32_t swz(uint32_t row, uint32_t k) {
    return row * 128u + ((((k >> 3) ^ (row & 7)) << 4) | ((k & 7) * 2u));
}

// ============================================================================
// Precompute kernels — split-K + atomics (R8 ncu: k_B1 43.2us @ occ 12.5%)
// ============================================================================

// zero the atomic-accumulated scratch (g_M, g_B1f), 786432 floats total
__global__ void k_zero() {
    size_t i = (size_t)blockIdx.x * 256 + threadIdx.x;   // grid 384 -> 98304 thr x f4x2
    float4 z = {0.f, 0.f, 0.f, 0.f};
    ((float4*)g_M)[i]   = z;
    ((float4*)g_B1f)[i] = z;
}

// M_i = Wo_i @ Wv_i, split-K: grid (4, 4, 12); z = i*2 + half (K chunk of 128)
__global__ void __launch_bounds__(256) k_M(const float* __restrict__ Wo,
                                           const float* __restrict__ Wv) {
    const int z  = blockIdx.z;
    const int i  = z >> 1;
    const int mbase = (z & 1) * 128;
    const int k0 = blockIdx.x * 64, e0 = blockIdx.y * 64;
    const int tid = threadIdx.x;
    __shared__ float sA[64][17];
    __shared__ float sB[16][65];
    const float* A  = Wo + i * 65536;
    const float* Bm = Wv + i * 65536;
    float acc[4][4] = {};
    const int ty = tid >> 4, tx = tid & 15;
    for (int m0 = mbase; m0 < mbase + 128; m0 += 16) {
        {
            int e = tid >> 4, mm = tid & 15;
#pragma unroll
            for (int r = 0; r < 4; r++)
                sA[r * 16 + e][mm] = A[(e0 + r * 16 + e) * 256 + m0 + mm];
        }
        {
            int mm = tid >> 6, kk = tid & 63;
#pragma unroll
            for (int r = 0; r < 4; r++)
                sB[r * 4 + mm][kk] = Bm[(m0 + r * 4 + mm) * 256 + k0 + kk];
        }
        __syncthreads();
#pragma unroll
        for (int kk = 0; kk < 16; kk++) {
            float a[4], b[4];
#pragma unroll
            for (int x = 0; x < 4; x++) a[x] = sA[ty * 4 + x][kk];
#pragma unroll
            for (int x = 0; x < 4; x++) b[x] = sB[kk][tx * 4 + x];
#pragma unroll
            for (int x = 0; x < 4; x++)
#pragma unroll
                for (int y = 0; y < 4; y++) acc[x][y] += a[x] * b[y];
        }
        __syncthreads();
    }
#pragma unroll
    for (int x = 0; x < 4; x++)
#pragma unroll
        for (int y = 0; y < 4; y++)
            atomicAdd(&g_M[i * 65536 + (e0 + ty * 4 + x) * 256 + k0 + tx * 4 + y], acc[x][y]);
}

// c_i = Wo_i @ bv_i + bo_i
__global__ void k_cvec(const float* __restrict__ Wo, const float* __restrict__ bv,
                       const float* __restrict__ bo) {
    int i = blockIdx.x, e = threadIdx.x;
    const float* w = Wo + i * 65536 + e * 256;
    const float* b = bv + i * 256;
    float a0 = 0.f, a1 = 0.f, a2 = 0.f, a3 = 0.f;
#pragma unroll 4
    for (int m = 0; m < 256; m += 4) {
        a0 += w[m + 0] * b[m + 0];
        a1 += w[m + 1] * b[m + 1];
        a2 += w[m + 2] * b[m + 2];
        a3 += w[m + 3] * b[m + 3];
    }
    g_cvec[i * 256 + e] = bo[i * 256 + e] + (a0 + a1) + (a2 + a3);
}

// fold term: g_B1f[n][k] += sum_e W1[n][q*256+e] * M[idx(r,q)][e][k%256]
// split: grid (12, 8, 4); z>>1 selects which q (of the two != r), z&1 selects e-half
__global__ void __launch_bounds__(256) k_B1(const float* __restrict__ W1) {
    const int k0 = blockIdx.x * 64, n0 = blockIdx.y * 64;
    const int r = k0 >> 8;
    const int kp0 = k0 & 255;
    const int z = blockIdx.z;
    const int qi = z >> 1;
    const int q = (qi == 0) ? (r == 0 ? 1 : 0) : (r == 2 ? 1 : 2);
    // module index: kv-input r, query q -> c_IDX[r][q] inlined:
    // (r,q): (0,1)->2 (0,2)->4 (1,0)->0 (1,2)->5 (2,0)->1 (2,1)->3
    const int midx = (r == 0) ? (q == 1 ? 2 : 4)
                   : (r == 1) ? (q == 0 ? 0 : 5)
                              : (q == 0 ? 1 : 3);
    const int ebase = (z & 1) * 128;
    const int tid = threadIdx.x;
    __shared__ float sA[64][17];
    __shared__ float sB[16][65];
    float acc[4][4] = {};
    const int ty = tid >> 4, tx = tid & 15;
    const float* Mb = g_M + midx * 65536;
    for (int e0 = ebase; e0 < ebase + 128; e0 += 16) {
        {
            int n = tid >> 4, ee = tid & 15;
#pragma unroll
            for (int rr = 0; rr < 4; rr++)
                sA[rr * 16 + n][ee] = W1[(n0 + rr * 16 + n) * KIN + q * 256 + e0 + ee];
        }
        {
            int ee = tid >> 6, kk = tid & 63;
#pragma unroll
            for (int rr = 0; rr < 4; rr++)
                sB[rr * 4 + ee][kk] = Mb[(e0 + rr * 4 + ee) * 256 + kp0 + kk];
        }
        __syncthreads();
#pragma unroll
        for (int kk = 0; kk < 16; kk++) {
            float a[4], b[4];
#pragma unroll
            for (int x = 0; x < 4; x++) a[x] = sA[ty * 4 + x][kk];
#pragma unroll
            for (int x = 0; x < 4; x++) b[x] = sB[kk][tx * 4 + x];
#pragma unroll
            for (int x = 0; x < 4; x++)
#pragma unroll
                for (int y = 0; y < 4; y++) acc[x][y] += a[x] * b[y];
        }
        __syncthreads();
    }
#pragma unroll
    for (int x = 0; x < 4; x++)
#pragma unroll
        for (int y = 0; y < 4; y++) {
            int n = n0 + ty * 4 + x, k = k0 + tx * 4 + y;
            atomicAdd(&g_B1f[n * KIN + k], acc[x][y]);
        }
}

// finalize: B1h = fp16(W1 + fold)
__global__ void k_B1fin(const float* __restrict__ W1) {
    int idx = blockIdx.x * 256 + threadIdx.x;   // grid 1536
    g_B1h[idx] = __float2half_rn(W1[idx] + g_B1f[idx]);
}

// b1eff[n] = b1[n] + sum_j csum[j] * W1[n][j]
__global__ void __launch_bounds__(256) k_b1eff(const float* __restrict__ W1,
                                               const float* __restrict__ b1) {
    const int n = blockIdx.x;
    const int tid = threadIdx.x;
    float p = 0.f;
#pragma unroll
    for (int jj = 0; jj < 3; jj++) {
        int j = jj * 256 + tid;
        int q = j >> 8, e = j & 255;
        float cs = g_cvec[(2 * q) * 256 + e] + g_cvec[(2 * q + 1) * 256 + e];
        p += cs * W1[n * KIN + j];
    }
    __shared__ float red[256];
    red[tid] = p;
    __syncthreads();
#pragma unroll
    for (int s = 128; s > 0; s >>= 1) {
        if (tid < s) red[tid] += red[tid + s];
        __syncthreads();
    }
    if (tid == 0) g_b1eff[n] = b1[n] + red[0];
}

// W2 -> fp16
__global__ void k_W2h(const float* __restrict__ W2) {
    int idx = blockIdx.x * 256 + threadIdx.x;
    if (idx < EDIM * HIDN) g_W2h[idx] = __float2half_rn(W2[idx]);
}

// ============================================================================
// GEMM1 (R6 winner): hidden[B,512] = relu(X[B,768] @ B1h^T + b1eff)
// 256 thr, tile 128x128, warp tile 64x32, K-chunk 64, double-buffered, occ 2
// ============================================================================
#define SM_A0 0
#define SM_A1 16384
#define SM_B0 32768
#define SM_B1 49152
#define SMEM_G 65536

__global__ void __launch_bounds__(256, 2)
gemm1(const float* __restrict__ gE, const float* __restrict__ dE,
      const float* __restrict__ cE) {
    extern __shared__ char smem[];
    const uint32_t sb = smem_u32(smem);
    const int tid = threadIdx.x;
    const int wid = tid >> 5, lane = tid & 31;
    const int m0 = blockIdx.y * 128;
    const int n0 = blockIdx.x * 128;
    const int wm = (wid >> 2) * 64;
    const int wn = (wid & 3) * 32;
    const float* srcs[3] = {gE, dE, cE};

    float acc[4][4][4];
#pragma unroll
    for (int i = 0; i < 4; i++)
#pragma unroll
        for (int j = 0; j < 4; j++)
#pragma unroll
            for (int v = 0; v < 4; v++) acc[i][j][v] = 0.f;

    const int a_row[8] = { (0*256+tid) >> 4, (1*256+tid) >> 4, (2*256+tid) >> 4, (3*256+tid) >> 4,
                           (4*256+tid) >> 4, (5*256+tid) >> 4, (6*256+tid) >> 4, (7*256+tid) >> 4 };
    const int a_c4 = tid & 15;

    uint2 ah[8];   // A fragment converted to fp16 at load time

    // prologue: buffer 0 (kc = 0)
    {
        const float* src = srcs[0] + (size_t)m0 * 256;
#pragma unroll
        for (int i = 0; i < 8; i++) {
            float4 f = *(const float4*)(src + (size_t)a_row[i] * 256 + a_c4 * 4);
            __half2 h0 = __floats2half2_rn(f.x, f.y);
            __half2 h1 = __floats2half2_rn(f.z, f.w);
            ah[i].x = *(uint32_t*)&h0;
            ah[i].y = *(uint32_t*)&h1;
        }
#pragma unroll
        for (int i = 0; i < 8; i++)
            *(uint2*)(smem + SM_A0 + swz(a_row[i], a_c4 * 4)) = ah[i];
#pragma unroll
        for (int i = 0; i < 4; i++) {
            int idx = i * 256 + tid;
            int row = idx >> 3, c = idx & 7;
            cp_async16(sb + SM_B0 + swz(row, c * 8), g_B1h + (size_t)(n0 + row) * KIN + c * 8);
        }
        cp_commit();
        cp_wait0();
        __syncthreads();
    }

    const int NITER = 12;
    for (int kc = 0; kc < NITER; kc++) {
        const uint32_t Abase = sb + (kc & 1 ? SM_A1 : SM_A0);
        const uint32_t Bbase = sb + (kc & 1 ? SM_B1 : SM_B0);
        const int nxt = kc + 1;
        const uint32_t AbaseN = sb + (nxt & 1 ? SM_A1 : SM_A0);
        const uint32_t BbaseN = sb + (nxt & 1 ? SM_B1 : SM_B0);

        if (nxt < NITER) {
            const float* src = srcs[nxt >> 2] + (size_t)m0 * 256 + (nxt & 3) * 64;
#pragma unroll
            for (int i = 0; i < 8; i++) {
                float4 f = *(const float4*)(src + (size_t)a_row[i] * 256 + a_c4 * 4);
                __half2 h0 = __floats2half2_rn(f.x, f.y);
                __half2 h1 = __floats2half2_rn(f.z, f.w);
                ah[i].x = *(uint32_t*)&h0;
                ah[i].y = *(uint32_t*)&h1;
            }
#pragma unroll
            for (int i = 0; i < 4; i++) {
                int idx = i * 256 + tid;
                int row = idx >> 3, c = idx & 7;
                cp_async16(BbaseN + swz(row, c * 8),
                           g_B1h + (size_t)(n0 + row) * KIN + nxt * 64 + c * 8);
            }
            cp_commit();
        }

        // compute on current buffers
#pragma unroll
        for (int ks = 0; ks < 64; ks += 16) {
            uint32_t a[4][4], b[8];
#pragma unroll
            for (int t = 0; t < 4; t++) {
                uint32_t row = wm + t * 16 + (lane & 15);
                uint32_t kk  = ks + (lane >> 4) * 8;
                ldm_x4(a[t][0], a[t][1], a[t][2], a[t][3], Abase + swz(row, kk));
            }
#pragma unroll
            for (int h = 0; h < 2; h++) {
                int g = lane >> 3, ri = lane & 7;
                uint32_t nrow = wn + h * 16 + (g >> 1) * 8 + ri;
                uint32_t kk   = ks + (g & 1) * 8;
                ldm_x4(b[h * 4 + 0], b[h * 4 + 1], b[h * 4 + 2], b[h * 4 + 3],
                       Bbase + swz(nrow, kk));
            }
#pragma unroll
            for (int mt = 0; mt < 4; mt++)
#pragma unroll
                for (int nt = 0; nt < 4; nt++)
                    mma16816(acc[mt][nt], a[mt][0], a[mt][1], a[mt][2], a[mt][3],
                             b[nt * 2], b[nt * 2 + 1]);
        }

        if (nxt < NITER) {
#pragma unroll
            for (int i = 0; i < 8; i++)
                *(uint2*)((char*)smem + (AbaseN - sb) + swz(a_row[i], a_c4 * 4)) = ah[i];
            cp_wait0();
        }
        __syncthreads();
    }

    // epilogue: relu(acc + b1eff) -> fp16 g_H
#pragma unroll
    for (int mt = 0; mt < 4; mt++) {
#pragma unroll
        for (int nt = 0; nt < 4; nt++) {
            int n = n0 + wn + nt * 8 + (lane & 3) * 2;
            float bia0 = g_b1eff[n], bia1 = g_b1eff[n + 1];
            int r0 = m0 + wm + mt * 16 + (lane >> 2);
            float v0 = fmaxf(acc[mt][nt][0] + bia0, 0.f);
            float v1 = fmaxf(acc[mt][nt][1] + bia1, 0.f);
            float v2 = fmaxf(acc[mt][nt][2] + bia0, 0.f);
            float v3 = fmaxf(acc[mt][nt][3] + bia1, 0.f);
            __half2 h01 = __floats2half2_rn(v0, v1);
            __half2 h23 = __floats2half2_rn(v2, v3);
            *(__half2*)(g_H + (size_t)r0 * HIDN + n)       = h01;
            *(__half2*)(g_H + (size_t)(r0 + 8) * HIDN + n) = h23;
        }
    }
}

// ============================================================================
// GEMM2 (R6 winner): out[B,256] = g_H[B,512] @ W2h^T + b2, fp32 out, occ 2
// ============================================================================
__global__ void __launch_bounds__(256, 2)
gemm2(const float* __restrict__ b2, float* __restrict__ out) {
    extern __shared__ char smem[];
    const uint32_t sb = smem_u32(smem);
    const int tid = threadIdx.x;
    const int wid = tid >> 5, lane = tid & 31;
    const int m0 = blockIdx.y * 128;
    const int n0 = blockIdx.x * 128;
    const int wm = (wid >> 2) * 64;
    const int wn = (wid & 3) * 32;

    float acc[4][4][4];
#pragma unroll
    for (int i = 0; i < 4; i++)
#pragma unroll
        for (int j = 0; j < 4; j++)
#pragma unroll
            for (int v = 0; v < 4; v++) acc[i][j][v] = 0.f;

    // prologue buffer 0
    {
#pragma unroll
        for (int i = 0; i < 4; i++) {
            int idx = i * 256 + tid;
            int row = idx >> 3, c = idx & 7;
            cp_async16(sb + SM_A0 + swz(row, c * 8), g_H + (size_t)(m0 + row) * HIDN + c * 8);
            cp_async16(sb + SM_B0 + swz(row, c * 8), g_W2h + (size_t)(n0 + row) * HIDN + c * 8);
        }
        cp_commit();
        cp_wait0();
        __syncthreads();
    }

    const int NITER = 8;
    for (int kc = 0; kc < NITER; kc++) {
        const uint32_t Abase = sb + (kc & 1 ? SM_A1 : SM_A0);
        const uint32_t Bbase = sb + (kc & 1 ? SM_B1 : SM_B0);
        const int nxt = kc + 1;

        if (nxt < NITER) {
            uint32_t AbaseN = sb + (nxt & 1 ? SM_A1 : SM_A0);
            uint32_t BbaseN = sb + (nxt & 1 ? SM_B1 : SM_B0);
#pragma unroll
            for (int i = 0; i < 4; i++) {
                int idx = i * 256 + tid;
                int row = idx >> 3, c = idx & 7;
                cp_async16(AbaseN + swz(row, c * 8),
                           g_H + (size_t)(m0 + row) * HIDN + nxt * 64 + c * 8);
                cp_async16(BbaseN + swz(row, c * 8),
                           g_W2h + (size_t)(n0 + row) * HIDN + nxt * 64 + c * 8);
            }
            cp_commit();
        }

#pragma unroll
        for (int ks = 0; ks < 64; ks += 16) {
            uint32_t a[4][4], b[8];
#pragma unroll
            for (int t = 0; t < 4; t++) {
                uint32_t row = wm + t * 16 + (lane & 15);
                uint32_t kk  = ks + (lane >> 4) * 8;
                ldm_x4(a[t][0], a[t][1], a[t][2], a[t][3], Abase + swz(row, kk));
            }
#pragma unroll
            for (int h = 0; h < 2; h++) {
                int g = lane >> 3, ri = lane & 7;
                uint32_t nrow = wn + h * 16 + (g >> 1) * 8 + ri;
                uint32_t kk   = ks + (g & 1) * 8;
                ldm_x4(b[h * 4 + 0], b[h * 4 + 1], b[h * 4 + 2], b[h * 4 + 3],
                       Bbase + swz(nrow, kk));
            }
#pragma unroll
            for (int mt = 0; mt < 4; mt++)
#pragma unroll
                for (int nt = 0; nt < 4; nt++)
                    mma16816(acc[mt][nt], a[mt][0], a[mt][1], a[mt][2], a[mt][3],
                             b[nt * 2], b[nt * 2 + 1]);
        }

        if (nxt < NITER) cp_wait0();
        __syncthreads();
    }

    // epilogue: acc + b2 -> fp32 out
#pragma unroll
    for (int mt = 0; mt < 4; mt++) {
#pragma unroll
        for (int nt = 0; nt < 4; nt++) {
            int n = n0 + wn + nt * 8 + (lane & 3) * 2;
            float bia0 = b2[n], bia1 = b2[n + 1];
            int r0 = m0 + wm + mt * 16 + (lane >> 2);
            float2 o01 = { acc[mt][nt][0] + bia0, acc[mt][nt][1] + bia1 };
            float2 o23 = { acc[mt][nt][2] + bia0, acc[mt][nt][3] + bia1 };
            *(float2*)(out + (size_t)r0 * EDIM + n)       = o01;
            *(float2*)(out + (size_t)(r0 + 8) * EDIM + n) = o23;
        }
    }
}

// ============================================================================
// kernel_launch
// Input order: g, d, c, Wq, Wk, Wv, bq, bk, bv, Wo, bo, W1, b1, W2, b2
// ============================================================================
extern "C" void kernel_launch(void* const* d_in, const int* in_sizes, int n_in,
                              void* d_out, int out_size) {
    const float* g  = (const float*)d_in[0];
    const float* dd = (const float*)d_in[1];
    const float* cc = (const float*)d_in[2];
    const float* Wv = (const float*)d_in[5];
    const float* bv = (const float*)d_in[8];
    const float* Wo = (const float*)d_in[9];
    const float* bo = (const float*)d_in[10];
    const float* W1 = (const float*)d_in[11];
    const float* b1 = (const float*)d_in[12];
    const float* W2 = (const float*)d_in[13];
    const float* b2 = (const float*)d_in[14];
    const int B = in_sizes[0] / EDIM;

    // Precompute: zero scratch, then split-K folds
    k_zero <<<384, 256>>>();                       // g_M, g_B1f = 0
    k_cvec <<<6, 256>>>(Wo, bv, bo);
    k_M    <<<dim3(4, 4, 12), 256>>>(Wo, Wv);      // split-K x2
    k_B1   <<<dim3(12, 8, 4), 256>>>(W1);          // split-K x4 (per-q, per-e-half)
    k_b1eff<<<HIDN, 256>>>(W1, b1);
    k_B1fin<<<1536, 256>>>(W1);
    k_W2h  <<<512, 256>>>(W2);

    cudaFuncSetAttribute(gemm1, cudaFuncAttributeMaxDynamicSharedMemorySize, SMEM_G);
    cudaFuncSetAttribute(gemm2, cudaFuncAttributeMaxDynamicSharedMemorySize, SMEM_G);

    gemm1<<<dim3(4, B / 128), 256, SMEM_G>>>(g, dd, cc);
    gemm2<<<dim3(2, B / 128), 256, SMEM_G>>>(b2, (float*)d_out);
}